// round 3
// baseline (speedup 1.0000x reference)
#include <cuda_runtime.h>
#include <cuda_bf16.h>
#include <cstdint>

// ---------------------------------------------------------------------------
// WordGraphNet: 2-layer weighted GraphConv, CSR pull-side aggregation.
//   layer(h,W,b): Wh = h@W + b ; s = segsum(Wh[src]*ew, dst) ; out = s/max(deg,1)
//   out = layer2( leaky_relu(layer1(x)) )
// Edge list identical for both layers -> build CSR (sorted by dst) once.
// ---------------------------------------------------------------------------

#define MAX_NODES 50000
#define MAX_EDGES 1200000
#define HID 64
#define NEG_SLOPE 0.01f
#define SCAN_T 1024

__device__ float g_Wh[MAX_NODES * HID];       // projected features
__device__ float g_h1[MAX_NODES * HID];       // layer-1 output
__device__ int   g_cnt[MAX_NODES];            // per-dst degree (histogram)
__device__ int   g_off[MAX_NODES + 1];        // CSR offsets
__device__ int   g_cursor[MAX_NODES];         // fill cursors
__device__ int2  g_csr[MAX_EDGES];            // {src, float_bits(w)} sorted by dst

__device__ __forceinline__ float leaky(float v) {
    return v > 0.f ? v : NEG_SLOPE * v;
}

// ---------------------------------------------------------------------------
// CSR build
// ---------------------------------------------------------------------------
__global__ void hist_kernel(const int* __restrict__ dst, int* __restrict__ cnt,
                            int n_edges) {
    int e = blockIdx.x * blockDim.x + threadIdx.x;
    if (e < n_edges) atomicAdd(cnt + __ldg(dst + e), 1);
}

// Single-block exclusive scan over cnt[0..n) -> off, cursor; off[n] = total.
__global__ __launch_bounds__(SCAN_T)
void scan_kernel(const int* __restrict__ cnt, int* __restrict__ off,
                 int* __restrict__ cursor, int n) {
    __shared__ int sums[SCAN_T];
    int t = threadIdx.x;
    int ch = (n + SCAN_T - 1) / SCAN_T;
    int begin = min(t * ch, n);
    int end   = min(begin + ch, n);

    int s = 0;
    for (int i = begin; i < end; i++) s += __ldg(cnt + i);
    sums[t] = s;
    __syncthreads();

    for (int d = 1; d < SCAN_T; d <<= 1) {
        int v = (t >= d) ? sums[t - d] : 0;
        __syncthreads();
        sums[t] += v;
        __syncthreads();
    }

    int run = (t == 0) ? 0 : sums[t - 1];
    for (int i = begin; i < end; i++) {
        off[i] = run;
        cursor[i] = run;
        run += __ldg(cnt + i);
    }
    if (t == SCAN_T - 1) off[n] = sums[SCAN_T - 1];
}

__global__ void fill_kernel(const int* __restrict__ src, const int* __restrict__ dst,
                            const float* __restrict__ ew, int* __restrict__ cursor,
                            int2* __restrict__ csr, int n_edges) {
    int e = blockIdx.x * blockDim.x + threadIdx.x;
    if (e >= n_edges) return;
    int d = __ldg(dst + e);
    int pos = atomicAdd(cursor + d, 1);
    csr[pos] = make_int2(__ldg(src + e), __float_as_int(__ldg(ew + e)));
}

// ---------------------------------------------------------------------------
// Tiled GEMM + bias: out[n][64] = H[n][K] @ W[K][64] + b
// 128 threads, tile 128 nodes x 64 cols, 8x8 register tile per thread.
// ---------------------------------------------------------------------------
#define TILE_M 128
#define KC 32
#define KCP 36

template <int K>
__global__ __launch_bounds__(128)
void gemm_tile_kernel(const float* __restrict__ H,
                      const float* __restrict__ Wg,
                      const float* __restrict__ bg,
                      float* __restrict__ out,
                      int n_nodes) {
    __shared__ float Hs[TILE_M * KCP];
    __shared__ float Ws[KC * HID];

    const int tid = threadIdx.x;
    const int tx = tid & 7;
    const int ty = tid >> 3;
    const int node0 = blockIdx.x * TILE_M;

    float acc[8][8];
#pragma unroll
    for (int i = 0; i < 8; i++)
#pragma unroll
        for (int j = 0; j < 8; j++) acc[i][j] = 0.f;

    for (int kc0 = 0; kc0 < K; kc0 += KC) {
        {
            const float4* Wg4 = reinterpret_cast<const float4*>(Wg + kc0 * HID);
            float4* Ws4w = reinterpret_cast<float4*>(Ws);
#pragma unroll
            for (int f = tid; f < KC * 16; f += 128)
                Ws4w[f] = __ldg(Wg4 + f);
        }
#pragma unroll
        for (int f = tid; f < TILE_M * (KC / 4); f += 128) {
            int m = f >> 3;
            int j = f & 7;
            int node = node0 + m;
            float4 v = make_float4(0.f, 0.f, 0.f, 0.f);
            if (node < n_nodes)
                v = __ldg(reinterpret_cast<const float4*>(H + (size_t)node * K + kc0) + j);
            *reinterpret_cast<float4*>(Hs + m * KCP + 4 * j) = v;
        }
        __syncthreads();

        const float4* Ws4 = reinterpret_cast<const float4*>(Ws);
#pragma unroll 4
        for (int kk = 0; kk < KC; kk++) {
            float h[8];
#pragma unroll
            for (int i = 0; i < 8; i++)
                h[i] = Hs[(ty + 16 * i) * KCP + kk];
            float4 w0 = Ws4[kk * 16 + tx];
            float4 w1 = Ws4[kk * 16 + 8 + tx];
            float w[8] = {w0.x, w0.y, w0.z, w0.w, w1.x, w1.y, w1.z, w1.w};
#pragma unroll
            for (int i = 0; i < 8; i++)
#pragma unroll
                for (int j = 0; j < 8; j++)
                    acc[i][j] += h[i] * w[j];
        }
        __syncthreads();
    }

    float4 b0 = __ldg(reinterpret_cast<const float4*>(bg) + tx);
    float4 b1 = __ldg(reinterpret_cast<const float4*>(bg) + 8 + tx);
#pragma unroll
    for (int i = 0; i < 8; i++) {
        int node = node0 + ty + 16 * i;
        if (node < n_nodes) {
            float4 o0 = make_float4(acc[i][0] + b0.x, acc[i][1] + b0.y,
                                    acc[i][2] + b0.z, acc[i][3] + b0.w);
            float4 o1 = make_float4(acc[i][4] + b1.x, acc[i][5] + b1.y,
                                    acc[i][6] + b1.z, acc[i][7] + b1.w);
            *reinterpret_cast<float4*>(out + (size_t)node * HID + tx * 4) = o0;
            *reinterpret_cast<float4*>(out + (size_t)node * HID + 32 + tx * 4) = o1;
        }
    }
}

// ---------------------------------------------------------------------------
// Pull-side aggregate: out[n] = act( (1/max(deg,1)) * sum_e w_e * Wh[src_e] )
// 16 threads per node, one float4 per thread. 2-edge unrolled for MLP.
// Fuses normalize (+leaky for layer 1). Writes every output element once.
// ---------------------------------------------------------------------------
template <bool DO_LEAKY>
__global__ __launch_bounds__(256)
void aggregate_kernel(const float4* __restrict__ Wh4,
                      const int2* __restrict__ csr,
                      const int* __restrict__ off,
                      float* __restrict__ out,
                      int n_nodes) {
    int gid = blockIdx.x * blockDim.x + threadIdx.x;
    int node = gid >> 4;
    int c4 = gid & 15;
    if (node >= n_nodes) return;

    int e   = __ldg(off + node);
    int end = __ldg(off + node + 1);
    int deg = end - e;

    float4 acc = make_float4(0.f, 0.f, 0.f, 0.f);
    for (; e + 2 <= end; e += 2) {
        int2 a = __ldg(csr + e);
        int2 b = __ldg(csr + e + 1);
        float4 va = __ldg(Wh4 + (size_t)a.x * 16 + c4);
        float4 vb = __ldg(Wh4 + (size_t)b.x * 16 + c4);
        float wa = __int_as_float(a.y);
        float wb = __int_as_float(b.y);
        acc.x += va.x * wa + vb.x * wb;
        acc.y += va.y * wa + vb.y * wb;
        acc.z += va.z * wa + vb.z * wb;
        acc.w += va.w * wa + vb.w * wb;
    }
    if (e < end) {
        int2 a = __ldg(csr + e);
        float4 va = __ldg(Wh4 + (size_t)a.x * 16 + c4);
        float wa = __int_as_float(a.y);
        acc.x += va.x * wa;
        acc.y += va.y * wa;
        acc.z += va.z * wa;
        acc.w += va.w * wa;
    }

    float inv = 1.0f / fmaxf((float)deg, 1.0f);
    acc.x *= inv; acc.y *= inv; acc.z *= inv; acc.w *= inv;
    if (DO_LEAKY) {
        acc.x = leaky(acc.x); acc.y = leaky(acc.y);
        acc.z = leaky(acc.z); acc.w = leaky(acc.w);
    }
    reinterpret_cast<float4*>(out)[gid] = acc;
}

// ---------------------------------------------------------------------------
// Launch
// ---------------------------------------------------------------------------
extern "C" void kernel_launch(void* const* d_in, const int* in_sizes, int n_in,
                              void* d_out, int out_size) {
    const float* x   = (const float*)d_in[0];
    const float* ew  = (const float*)d_in[1];
    const float* W1  = (const float*)d_in[2];
    const float* b1  = (const float*)d_in[3];
    const float* W2  = (const float*)d_in[4];
    const float* b2  = (const float*)d_in[5];
    const int*   src = (const int*)d_in[6];
    const int*   dst = (const int*)d_in[7];
    float*       out = (float*)d_out;

    int n_nodes = in_sizes[0] / 128;
    int n_edges = in_sizes[1];

    void *pWh_v, *pH1_v, *pCnt_v, *pOff_v, *pCur_v, *pCsr_v;
    cudaGetSymbolAddress(&pWh_v,  g_Wh);
    cudaGetSymbolAddress(&pH1_v,  g_h1);
    cudaGetSymbolAddress(&pCnt_v, g_cnt);
    cudaGetSymbolAddress(&pOff_v, g_off);
    cudaGetSymbolAddress(&pCur_v, g_cursor);
    cudaGetSymbolAddress(&pCsr_v, g_csr);
    float* pWh  = (float*)pWh_v;
    float* pH1  = (float*)pH1_v;
    int*   pCnt = (int*)pCnt_v;
    int*   pOff = (int*)pOff_v;
    int*   pCur = (int*)pCur_v;
    int2*  pCsr = (int2*)pCsr_v;

    int eb = (n_edges + 255) / 256;
    int gemm_blocks = (n_nodes + TILE_M - 1) / TILE_M;
    int agg_blocks = (n_nodes * 16 + 255) / 256;

    // CSR build (edges shared by both layers)
    cudaMemsetAsync(pCnt, 0, (size_t)n_nodes * sizeof(int));
    hist_kernel<<<eb, 256>>>(dst, pCnt, n_edges);
    scan_kernel<<<1, SCAN_T>>>(pCnt, pOff, pCur, n_nodes);
    fill_kernel<<<eb, 256>>>(src, dst, ew, pCur, pCsr, n_edges);

    // Layer 1
    gemm_tile_kernel<128><<<gemm_blocks, 128>>>(x, W1, b1, pWh, n_nodes);
    aggregate_kernel<true><<<agg_blocks, 256>>>(
        (const float4*)pWh, pCsr, pOff, pH1, n_nodes);

    // Layer 2
    gemm_tile_kernel<64><<<gemm_blocks, 128>>>(pH1, W2, b2, pWh, n_nodes);
    aggregate_kernel<false><<<agg_blocks, 256>>>(
        (const float4*)pWh, pCsr, pOff, out, n_nodes);
}